// round 1
// baseline (speedup 1.0000x reference)
#include <cuda_runtime.h>
#include <cuda_bf16.h>
#include <cstdint>

// Problem constants
#define BB 4
#define NN 4096
#define CC 64
#define BN (BB * NN)

#define TARGETF 560.0f
#define MIN_BOXF 5.0f
#define IOU_THRF 0.2f
#define CONF_THRF 0.001f
#define BOX_CONF_THRF 0.01f
#define MAX_WHF 4096.0f

// ------------------------- scratch (static device memory; no allocs) -------
__device__ float4 g_cbox[BN];     // clipped boxes, original order
__device__ float  g_conf[BN];
__device__ int    g_cls[BN];
__device__ int    g_valid[BN];

__device__ float4 g_sbox[BN];     // sorted by (conf desc, idx asc)
__device__ float  g_sconf[BN];
__device__ int    g_scls[BN];
__device__ int    g_svalid[BN];

__device__ int g_list[BB * CC * NN];   // per (b,c): sorted ranks of members
__device__ int g_cnt[BB * CC];

// ------------------------- K0: zero output ---------------------------------
__global__ void k0_zero(float* out, int n) {
    int i = blockIdx.x * blockDim.x + threadIdx.x;
    if (i < n) out[i] = 0.0f;
}

// ------------------------- K1: conf / argmax / clip / valid ----------------
// One warp per box. Exact fp32 ops to match XLA.
__global__ void k1_prepare(const float* __restrict__ boxes,
                           const float* __restrict__ scores,
                           const float* __restrict__ preds) {
    int box  = (blockIdx.x * blockDim.x + threadIdx.x) >> 5;
    int lane = threadIdx.x & 31;
    if (box >= BN) return;

    const float* p = preds + (size_t)box * CC;
    float s = scores[box];

    // cls_conf = preds * score, elementwise (exact rn multiply), then
    // max with first-index tie-break (matches jnp.max / jnp.argmax).
    float v0 = __fmul_rn(p[lane], s);
    float v1 = __fmul_rn(p[lane + 32], s);
    float bv; int bi;
    if (v1 > v0) { bv = v1; bi = lane + 32; } else { bv = v0; bi = lane; }

    #pragma unroll
    for (int o = 16; o > 0; o >>= 1) {
        float ov = __shfl_down_sync(0xffffffffu, bv, o);
        int   oi = __shfl_down_sync(0xffffffffu, bi, o);
        if (ov > bv || (ov == bv && oi < bi)) { bv = ov; bi = oi; }
    }

    if (lane == 0) {
        float4 bx = reinterpret_cast<const float4*>(boxes)[box];
        float x1 = fminf(fmaxf(bx.x, 0.0f), TARGETF);
        float y1 = fminf(fmaxf(bx.y, 0.0f), TARGETF);
        float x2 = fminf(fmaxf(bx.z, 0.0f), TARGETF);
        float y2 = fminf(fmaxf(bx.w, 0.0f), TARGETF);
        float w = __fsub_rn(x2, x1);
        float h = __fsub_rn(y2, y1);
        int valid = (s > BOX_CONF_THRF) && (w > MIN_BOXF) && (h > MIN_BOXF)
                    && (bv > CONF_THRF);
        g_cbox[box]  = make_float4(x1, y1, x2, y2);
        g_conf[box]  = bv;
        g_cls[box]   = bi;
        g_valid[box] = valid;
    }
}

// ------------------------- K2: per-batch stable bitonic sort ----------------
// Key (ascending) = (~float_ordered(score_key) << 32) | idx
// => descending by conf, stable (ascending idx) on ties. Matches jnp.argsort.
__global__ void k2_sort() {
    int b = blockIdx.x;
    __shared__ unsigned long long sk[NN];
    int tid = threadIdx.x;

    for (int i = tid; i < NN; i += blockDim.x) {
        int src = b * NN + i;
        float skey = g_valid[src] ? g_conf[src] : -1.0f;
        unsigned int u = __float_as_uint(skey);
        u = (u & 0x80000000u) ? ~u : (u | 0x80000000u);   // total order map
        sk[i] = ((unsigned long long)(~u) << 32) | (unsigned int)i;
    }
    __syncthreads();

    for (int k = 2; k <= NN; k <<= 1) {
        for (int j = k >> 1; j > 0; j >>= 1) {
            for (int i = tid; i < NN; i += blockDim.x) {
                int ixj = i ^ j;
                if (ixj > i) {
                    bool up = ((i & k) == 0);
                    unsigned long long a = sk[i], c = sk[ixj];
                    if ((a > c) == up) { sk[i] = c; sk[ixj] = a; }
                }
            }
            __syncthreads();
        }
    }

    for (int r = tid; r < NN; r += blockDim.x) {
        int n   = (int)(sk[r] & 0xffffffffull);
        int src = b * NN + n;
        int dst = b * NN + r;
        g_sbox[dst]   = g_cbox[src];
        g_sconf[dst]  = g_conf[src];
        g_scls[dst]   = g_cls[src];
        g_svalid[dst] = g_valid[src];
    }
}

// ------------------------- K3: stable per-class compaction -----------------
// One warp per (batch, class): scan sorted ranks, ballot-compact.
__global__ void k3_lists() {
    int b    = blockIdx.x >> 1;
    int c    = (blockIdx.x & 1) * 32 + (threadIdx.x >> 5);
    int lane = threadIdx.x & 31;
    int cnt  = 0;
    int base = (b * CC + c) * NN;
    unsigned lt = (1u << lane) - 1u;

    for (int ch = 0; ch < NN / 32; ch++) {
        int pos = ch * 32 + lane;
        int idx = b * NN + pos;
        bool m = g_svalid[idx] && (g_scls[idx] == c);
        unsigned mask = __ballot_sync(0xffffffffu, m);
        if (m) g_list[base + cnt + __popc(mask & lt)] = pos;
        cnt += __popc(mask);
    }
    if (lane == 0) g_cnt[b * CC + c] = cnt;
}

// ------------------------- K4: per-(batch,class) greedy NMS ----------------
// Exact replication of reference IoU arithmetic INCLUDING the class-offset
// rounding (offsets up to 258048 change fp32 rounding of subtractions).
__global__ void k4_nms(float* __restrict__ out) {
    int bc = blockIdx.x;
    int b  = bc >> 6;
    int c  = bc & 63;
    int lane = threadIdx.x;
    int M = g_cnt[bc];
    if (M == 0) return;

    __shared__ unsigned char sup[NN];
    for (int i = lane; i < M; i += 32) sup[i] = 0;
    __syncwarp();

    const int* list = g_list + bc * NN;
    float off = (float)c * MAX_WHF;   // exact in fp32 (int * 2^12)

    for (int i = 0; i < M; i++) {
        if (sup[i]) continue;         // uniform across warp
        int pos = list[i];
        float4 bi = g_sbox[b * NN + pos];
        float ix1 = __fadd_rn(bi.x, off), iy1 = __fadd_rn(bi.y, off);
        float ix2 = __fadd_rn(bi.z, off), iy2 = __fadd_rn(bi.w, off);
        float ai  = __fmul_rn(__fsub_rn(ix2, ix1), __fsub_rn(iy2, iy1));

        if (lane == 0) {
            float* o = out + ((size_t)b * NN + pos) * 6;
            o[0] = bi.x; o[1] = bi.y; o[2] = bi.z; o[3] = bi.w;
            o[4] = g_sconf[b * NN + pos];
            o[5] = (float)c;
        }

        for (int j = i + 1 + lane; j < M; j += 32) {
            if (sup[j]) continue;
            int pj = list[j];
            float4 bj = g_sbox[b * NN + pj];
            float jx1 = __fadd_rn(bj.x, off), jy1 = __fadd_rn(bj.y, off);
            float jx2 = __fadd_rn(bj.z, off), jy2 = __fadd_rn(bj.w, off);
            float aj  = __fmul_rn(__fsub_rn(jx2, jx1), __fsub_rn(jy2, jy1));
            float ltx = fmaxf(ix1, jx1), lty = fmaxf(iy1, jy1);
            float rbx = fminf(ix2, jx2), rby = fminf(iy2, jy2);
            float w = fmaxf(__fsub_rn(rbx, ltx), 0.0f);
            float h = fmaxf(__fsub_rn(rby, lty), 0.0f);
            float inter = __fmul_rn(w, h);
            float denom = __fadd_rn(__fsub_rn(__fadd_rn(ai, aj), inter), 1e-9f);
            float iou   = __fdiv_rn(inter, denom);
            if (iou > IOU_THRF) sup[j] = 1;
        }
        __syncwarp();
    }
}

// ------------------------- launch ------------------------------------------
extern "C" void kernel_launch(void* const* d_in, const int* in_sizes, int n_in,
                              void* d_out, int out_size) {
    // Robust input identification by element count.
    const float *boxes = nullptr, *scores = nullptr, *preds = nullptr;
    for (int i = 0; i < n_in; i++) {
        if (in_sizes[i] == BN * 4)      boxes  = (const float*)d_in[i];
        else if (in_sizes[i] == BN)     scores = (const float*)d_in[i];
        else if (in_sizes[i] == BN * CC) preds = (const float*)d_in[i];
    }
    float* out = (float*)d_out;

    k0_zero<<<(out_size + 1023) / 1024, 1024>>>(out, out_size);
    k1_prepare<<<(BN * 32) / 1024, 1024>>>(boxes, scores, preds);
    k2_sort<<<BB, 1024>>>();
    k3_lists<<<BB * 2, 1024>>>();
    k4_nms<<<BB * CC, 32>>>(out);
}

// round 2
// speedup vs baseline: 1.5707x; 1.5707x over previous
#include <cuda_runtime.h>
#include <cuda_bf16.h>
#include <cstdint>

// Problem constants
#define BB 4
#define NN 4096
#define CC 64
#define BN (BB * NN)

#define TARGETF 560.0f
#define MIN_BOXF 5.0f
#define IOU_THRF 0.2f
#define CONF_THRF 0.001f
#define BOX_CONF_THRF 0.01f
#define MAX_WHF 4096.0f

// ------------------------- scratch (static device memory; no allocs) -------
__device__ float4 g_cbox[BN];     // clipped boxes, original order
__device__ float  g_conf[BN];
__device__ int    g_cls[BN];
__device__ int    g_valid[BN];

__device__ float4 g_sbox[BN];     // sorted by (conf desc, idx asc)
__device__ float  g_sconf[BN];
__device__ __align__(128) unsigned char g_tag[BN];  // valid ? cls : 255

// ------------------------- K0: zero output ---------------------------------
__global__ void k0_zero(float* out, int n) {
    int i = blockIdx.x * blockDim.x + threadIdx.x;
    if (i < n) out[i] = 0.0f;
}

// ------------------------- K1: conf / argmax / clip / valid ----------------
__global__ void k1_prepare(const float* __restrict__ boxes,
                           const float* __restrict__ scores,
                           const float* __restrict__ preds) {
    int box  = (blockIdx.x * blockDim.x + threadIdx.x) >> 5;
    int lane = threadIdx.x & 31;
    if (box >= BN) return;

    const float* p = preds + (size_t)box * CC;
    float s = scores[box];

    float v0 = __fmul_rn(p[lane], s);
    float v1 = __fmul_rn(p[lane + 32], s);
    float bv; int bi;
    if (v1 > v0) { bv = v1; bi = lane + 32; } else { bv = v0; bi = lane; }

    #pragma unroll
    for (int o = 16; o > 0; o >>= 1) {
        float ov = __shfl_down_sync(0xffffffffu, bv, o);
        int   oi = __shfl_down_sync(0xffffffffu, bi, o);
        if (ov > bv || (ov == bv && oi < bi)) { bv = ov; bi = oi; }
    }

    if (lane == 0) {
        float4 bx = reinterpret_cast<const float4*>(boxes)[box];
        float x1 = fminf(fmaxf(bx.x, 0.0f), TARGETF);
        float y1 = fminf(fmaxf(bx.y, 0.0f), TARGETF);
        float x2 = fminf(fmaxf(bx.z, 0.0f), TARGETF);
        float y2 = fminf(fmaxf(bx.w, 0.0f), TARGETF);
        float w = __fsub_rn(x2, x1);
        float h = __fsub_rn(y2, y1);
        int valid = (s > BOX_CONF_THRF) && (w > MIN_BOXF) && (h > MIN_BOXF)
                    && (bv > CONF_THRF);
        g_cbox[box]  = make_float4(x1, y1, x2, y2);
        g_conf[box]  = bv;
        g_cls[box]   = bi;
        g_valid[box] = valid;
    }
}

// ------------------------- K2: per-batch stable hybrid bitonic sort ---------
// Key (ascending) = (~float_ordered(score_key) << 32) | idx
// Register/shfl passes for stride j<=64 (warp owns 128 contiguous elements,
// 4 per thread); smem passes only for j>=128 (15 of 78 passes need a barrier).
__device__ __forceinline__ unsigned long long kmin(unsigned long long a,
                                                   unsigned long long b) {
    return a < b ? a : b;
}
__device__ __forceinline__ unsigned long long kmax(unsigned long long a,
                                                   unsigned long long b) {
    return a > b ? a : b;
}

__device__ __forceinline__ void stage_j(unsigned long long v[4], int i0,
                                        int lane, int k, int j) {
    if (j >= 4) {
        int m = j >> 2;                 // lane distance
        #pragma unroll
        for (int r = 0; r < 4; r++) {
            unsigned long long other = __shfl_xor_sync(0xffffffffu, v[r], m);
            bool up = (((i0 + r) & k) == 0);
            bool keepmin = (((lane & m) == 0) == up);
            v[r] = keepmin ? kmin(v[r], other) : kmax(v[r], other);
        }
    } else if (j == 2) {
        #pragma unroll
        for (int r = 0; r < 2; r++) {
            bool up = (((i0 + r) & k) == 0);
            unsigned long long a = v[r], c = v[r + 2];
            if ((a > c) == up) { v[r] = c; v[r + 2] = a; }
        }
    } else {                            // j == 1
        #pragma unroll
        for (int r = 0; r < 4; r += 2) {
            bool up = (((i0 + r) & k) == 0);
            unsigned long long a = v[r], c = v[r + 1];
            if ((a > c) == up) { v[r] = c; v[r + 1] = a; }
        }
    }
}

__global__ void k2_sort() {
    int b = blockIdx.x;
    __shared__ unsigned long long sk[NN];
    int tid  = threadIdx.x;
    int lane = tid & 31;
    int i0   = ((tid >> 5) << 7) + (lane << 2);   // warp-local 128-elem base

    #pragma unroll
    for (int u = 0; u < 4; u++) {
        int i = tid + u * 1024;
        int src = b * NN + i;
        float skey = g_valid[src] ? g_conf[src] : -1.0f;
        unsigned int x = __float_as_uint(skey);
        x = (x & 0x80000000u) ? ~x : (x | 0x80000000u);
        sk[i] = ((unsigned long long)(~x) << 32) | (unsigned int)i;
    }
    __syncthreads();

    // Phase A: k = 2..128 entirely in registers (28 passes, 0 barriers)
    {
        unsigned long long v[4];
        #pragma unroll
        for (int r = 0; r < 4; r++) v[r] = sk[i0 + r];
        #pragma unroll
        for (int k = 2; k <= 128; k <<= 1)
            for (int j = k >> 1; j >= 1; j >>= 1)
                stage_j(v, i0, lane, k, j);
        #pragma unroll
        for (int r = 0; r < 4; r++) sk[i0 + r] = v[r];
    }
    __syncthreads();

    // Phase B: k = 256..4096: smem passes for j>=128, register tail j<=64
    for (int k = 256; k <= NN; k <<= 1) {
        for (int j = k >> 1; j >= 128; j >>= 1) {
            #pragma unroll 2
            for (int u = 0; u < 2; u++) {
                int p   = tid + u * 1024;                    // pair id 0..2047
                int i   = ((p & ~(j - 1)) << 1) | (p & (j - 1));
                int ixj = i | j;
                bool up = ((i & k) == 0);
                unsigned long long a = sk[i], c = sk[ixj];
                if ((a > c) == up) { sk[i] = c; sk[ixj] = a; }
            }
            __syncthreads();
        }
        {
            unsigned long long v[4];
            #pragma unroll
            for (int r = 0; r < 4; r++) v[r] = sk[i0 + r];
            #pragma unroll
            for (int j = 64; j >= 1; j >>= 1)
                stage_j(v, i0, lane, k, j);
            #pragma unroll
            for (int r = 0; r < 4; r++) sk[i0 + r] = v[r];
        }
        __syncthreads();
    }

    // Epilogue: gather into sorted arrays + packed tag
    #pragma unroll
    for (int u = 0; u < 4; u++) {
        int r   = tid + u * 1024;
        int n   = (int)(sk[r] & 0xffffffffull);
        int src = b * NN + n;
        int dst = b * NN + r;
        g_sbox[dst]  = g_cbox[src];
        g_sconf[dst] = g_conf[src];
        g_tag[dst]   = g_valid[src] ? (unsigned char)g_cls[src]
                                    : (unsigned char)255;
    }
}

// ------------------------- K4: fused compaction + greedy NMS ----------------
// One warp-block per (batch, class). Build the stable member list from the
// packed tag bytes (vectorized __vcmpeq4 + warp scan), then greedy NMS.
__global__ void k4_nms(float* __restrict__ out) {
    int bc = blockIdx.x;
    int b  = bc >> 6;
    int c  = bc & 63;
    int lane = threadIdx.x;

    __shared__ int list[NN];
    __shared__ unsigned char sup[NN];

    const unsigned int* tw = (const unsigned int*)g_tag + b * (NN / 4);
    unsigned int cls4 = (unsigned int)c * 0x01010101u;
    int cnt = 0;

    #pragma unroll 4
    for (int ch = 0; ch < 32; ch++) {
        unsigned int wv = tw[ch * 32 + lane];           // 4 tags per lane
        unsigned int eq = __vcmpeq4(wv, cls4);          // 0xFF per match
        int c4 = __popc(eq) >> 3;
        int inc = c4;
        #pragma unroll
        for (int o = 1; o < 32; o <<= 1) {
            int t = __shfl_up_sync(0xffffffffu, inc, o);
            if (lane >= o) inc += t;
        }
        int total = __shfl_sync(0xffffffffu, inc, 31);
        int w = cnt + (inc - c4);
        int basepos = ch * 128 + lane * 4;
        #pragma unroll
        for (int t = 0; t < 4; t++)
            if ((eq >> (8 * t)) & 1u) list[w++] = basepos + t;
        cnt += total;
    }

    int M = cnt;
    if (M == 0) return;
    for (int i = lane; i < M; i += 32) sup[i] = 0;
    __syncwarp();

    float off = (float)c * MAX_WHF;    // exact in fp32

    for (int i = 0; i < M; i++) {
        if (sup[i]) continue;          // warp-uniform
        int pos = list[i];
        float4 bi = g_sbox[b * NN + pos];
        float ix1 = __fadd_rn(bi.x, off), iy1 = __fadd_rn(bi.y, off);
        float ix2 = __fadd_rn(bi.z, off), iy2 = __fadd_rn(bi.w, off);
        float ai  = __fmul_rn(__fsub_rn(ix2, ix1), __fsub_rn(iy2, iy1));

        if (lane == 0) {
            float* o = out + ((size_t)b * NN + pos) * 6;
            o[0] = bi.x; o[1] = bi.y; o[2] = bi.z; o[3] = bi.w;
            o[4] = g_sconf[b * NN + pos];
            o[5] = (float)c;
        }

        for (int j = i + 1 + lane; j < M; j += 32) {
            if (sup[j]) continue;
            int pj = list[j];
            float4 bj = g_sbox[b * NN + pj];
            float jx1 = __fadd_rn(bj.x, off), jy1 = __fadd_rn(bj.y, off);
            float jx2 = __fadd_rn(bj.z, off), jy2 = __fadd_rn(bj.w, off);
            float aj  = __fmul_rn(__fsub_rn(jx2, jx1), __fsub_rn(jy2, jy1));
            float ltx = fmaxf(ix1, jx1), lty = fmaxf(iy1, jy1);
            float rbx = fminf(ix2, jx2), rby = fminf(iy2, jy2);
            float w = fmaxf(__fsub_rn(rbx, ltx), 0.0f);
            float h = fmaxf(__fsub_rn(rby, lty), 0.0f);
            float inter = __fmul_rn(w, h);
            float denom = __fadd_rn(__fsub_rn(__fadd_rn(ai, aj), inter), 1e-9f);
            float iou   = __fdiv_rn(inter, denom);
            if (iou > IOU_THRF) sup[j] = 1;
        }
        __syncwarp();
    }
}

// ------------------------- launch ------------------------------------------
extern "C" void kernel_launch(void* const* d_in, const int* in_sizes, int n_in,
                              void* d_out, int out_size) {
    const float *boxes = nullptr, *scores = nullptr, *preds = nullptr;
    for (int i = 0; i < n_in; i++) {
        if (in_sizes[i] == BN * 4)       boxes  = (const float*)d_in[i];
        else if (in_sizes[i] == BN)      scores = (const float*)d_in[i];
        else if (in_sizes[i] == BN * CC) preds  = (const float*)d_in[i];
    }
    float* out = (float*)d_out;

    k0_zero<<<(out_size + 1023) / 1024, 1024>>>(out, out_size);
    k1_prepare<<<(BN * 32) / 1024, 1024>>>(boxes, scores, preds);
    k2_sort<<<BB, 1024>>>();
    k4_nms<<<BB * CC, 32>>>(out);
}